// round 1
// baseline (speedup 1.0000x reference)
#include <cuda_runtime.h>
#include <cstdint>

#define NNODES 100000
#define NEDGES 1600000
#define EPS 1e-12f

// ---------------- scratch (no allocations allowed) ----------------
__device__ float g_h[NNODES * 64];     // transformed features (layer1: 64, reused)
__device__ float g_agg[NNODES * 64];   // aggregation buffer (64-wide max)
__device__ float g_h2[NNODES * 32];    // layer2 output
__device__ float g_agg2[NNODES * 32];  // layer2 aggregation
__device__ float g_nw[NEDGES];         // normalized edge weights (per-layer reuse)
__device__ float g_degout[NNODES];
__device__ float g_degin[NNODES];
__device__ float g_deg[NNODES];

// ---------------- degree accumulation ----------------
__global__ void degrees_kernel(const int* __restrict__ src, const int* __restrict__ dst,
                               const float* __restrict__ w,
                               float* __restrict__ degout, float* __restrict__ degin, int E)
{
    int e = blockIdx.x * blockDim.x + threadIdx.x;
    if (e >= E) return;
    float wv = w[e];
    atomicAdd(&degout[src[e]], wv);
    atomicAdd(&degin[dst[e]], wv);
}

// nw = w / sqrt(max(outdeg[src]*indeg[dst], eps)); also deg[dst] += nw
__global__ void norm_kernel(const int* __restrict__ src, const int* __restrict__ dst,
                            const float* __restrict__ w, float* __restrict__ nw,
                            const float* __restrict__ degout, const float* __restrict__ degin,
                            float* __restrict__ deg, int E)
{
    int e = blockIdx.x * blockDim.x + threadIdx.x;
    if (e >= E) return;
    int s = src[e], d = dst[e];
    float v = w[e] * rsqrtf(fmaxf(degout[s] * degin[d], EPS));
    nw[e] = v;
    atomicAdd(&deg[d], v);
}

// ---------------- edge scatter: AGG[dst] += H[src] * nw ----------------
// TPE = F/4 threads per edge, float4 gather + vector RED (no return).
template <int F>
__global__ void scatter_kernel(const int* __restrict__ src, const int* __restrict__ dst,
                               const float* __restrict__ nw, const float* __restrict__ H,
                               float* __restrict__ AGG, int E)
{
    constexpr int TPE = F / 4;
    int t = blockIdx.x * blockDim.x + threadIdx.x;
    int e = t / TPE;
    if (e >= E) return;
    int g = t % TPE;
    int s = src[e], d = dst[e];
    float w = nw[e];
    float4 v = *(const float4*)&H[(size_t)s * F + g * 4];
    float* p = &AGG[(size_t)d * F + g * 4];
    asm volatile("red.global.add.v4.f32 [%0], {%1, %2, %3, %4};"
                 :: "l"(p), "f"(v.x * w), "f"(v.y * w), "f"(v.z * w), "f"(v.w * w)
                 : "memory");
}

// ---------------- finalize: OUT = AGG / max(deg,eps) + b ----------------
template <int F>
__global__ void finalize_kernel(const float* __restrict__ AGG, const float* __restrict__ deg,
                                const float* __restrict__ bias, float* __restrict__ OUT, int n)
{
    int t = blockIdx.x * blockDim.x + threadIdx.x;
    int total = n * (F / 4);
    if (t >= total) return;
    int r = t / (F / 4);
    int c = (t % (F / 4)) * 4;
    float inv = 1.0f / fmaxf(deg[r], EPS);
    float4 a = *(const float4*)&AGG[(size_t)r * F + c];
    float4 b4 = *(const float4*)&bias[c];
    float4 o;
    o.x = a.x * inv + b4.x;
    o.y = a.y * inv + b4.y;
    o.z = a.z * inv + b4.z;
    o.w = a.w * inv + b4.w;
    *(float4*)&OUT[(size_t)r * F + c] = o;
}

// ---------------- GEMM: H = X @ W  (M x K @ K x NOUT) ----------------
// 64 rows per block, full K staged in smem, 4-col x TM-row register blocking.
// FINAL: epilogue divides by max(deg,eps) and adds bias (layer-3 path).
template <int K, int NOUT, bool FINAL>
__global__ void gemm_kernel(const float* __restrict__ X, const float* __restrict__ W,
                            float* __restrict__ H, int M,
                            const float* __restrict__ deg, const float* __restrict__ bias)
{
    constexpr int BR = 64;
    constexpr int CT = NOUT / 4;   // column-thread groups (each = 4 cols)
    constexpr int RT = 256 / CT;   // row threads
    constexpr int TM = BR / RT;    // rows per thread
    constexpr int XS = K + 4;      // padded X tile stride (floats)

    extern __shared__ float sm[];
    float* sX = sm;                // BR * XS
    float* sW = sm + BR * XS;      // K * NOUT

    int tid = threadIdx.x;
    int row0 = blockIdx.x * BR;

    // stage X tile (zero-pad out-of-range rows)
    constexpr int XV = BR * K / 4;
    for (int i = tid; i < XV; i += 256) {
        int r = (i * 4) / K;
        int c = (i * 4) % K;
        float4 v = make_float4(0.f, 0.f, 0.f, 0.f);
        if (row0 + r < M) v = *(const float4*)&X[(size_t)(row0 + r) * K + c];
        *(float4*)&sX[r * XS + c] = v;
    }
    // stage W (entire matrix)
    constexpr int WV = K * NOUT / 4;
    for (int i = tid; i < WV; i += 256) {
        *(float4*)&sW[i * 4] = *(const float4*)&W[i * 4];
    }
    __syncthreads();

    int ct = tid % CT;
    int rt = tid / CT;

    float acc[TM][4];
#pragma unroll
    for (int m = 0; m < TM; m++)
#pragma unroll
        for (int j = 0; j < 4; j++) acc[m][j] = 0.f;

#pragma unroll 8
    for (int k = 0; k < K; k++) {
        float4 wv = *(const float4*)&sW[k * NOUT + ct * 4];
#pragma unroll
        for (int m = 0; m < TM; m++) {
            float xv = sX[(rt + m * RT) * XS + k];
            acc[m][0] += xv * wv.x;
            acc[m][1] += xv * wv.y;
            acc[m][2] += xv * wv.z;
            acc[m][3] += xv * wv.w;
        }
    }

#pragma unroll
    for (int m = 0; m < TM; m++) {
        int r = row0 + rt + m * RT;
        if (r < M) {
            float4 o;
            o.x = acc[m][0]; o.y = acc[m][1]; o.z = acc[m][2]; o.w = acc[m][3];
            if (FINAL) {
                float inv = 1.0f / fmaxf(deg[r], EPS);
                float4 b4 = *(const float4*)&bias[ct * 4];
                o.x = o.x * inv + b4.x;
                o.y = o.y * inv + b4.y;
                o.z = o.z * inv + b4.z;
                o.w = o.w * inv + b4.w;
            }
            *(float4*)&H[(size_t)r * NOUT + ct * 4] = o;
        }
    }
}

// ---------------- host ----------------
static inline int cdiv(int a, int b) { return (a + b - 1) / b; }

extern "C" void kernel_launch(void* const* d_in, const int* in_sizes, int n_in,
                              void* d_out, int out_size)
{
    const float* x    = (const float*)d_in[0];
    const int*   src1 = (const int*)d_in[1];
    const int*   dst1 = (const int*)d_in[2];
    const float* w1   = (const float*)d_in[3];
    const int*   src2 = (const int*)d_in[4];
    const int*   dst2 = (const int*)d_in[5];
    const float* w2   = (const float*)d_in[6];
    const int*   src3 = (const int*)d_in[7];
    const int*   dst3 = (const int*)d_in[8];
    const float* w3   = (const float*)d_in[9];
    const float* W1   = (const float*)d_in[10];
    const float* b1   = (const float*)d_in[11];
    const float* W2   = (const float*)d_in[12];
    const float* b2   = (const float*)d_in[13];
    const float* W3   = (const float*)d_in[14];
    const float* b3   = (const float*)d_in[15];
    float* out = (float*)d_out;

    const int n  = in_sizes[0] / 128;
    const int e1 = in_sizes[1];
    const int e2 = in_sizes[4];
    const int e3 = in_sizes[7];

    float *h, *agg, *h2, *agg2, *nw, *dgo, *dgi, *dg;
    cudaGetSymbolAddress((void**)&h,    g_h);
    cudaGetSymbolAddress((void**)&agg,  g_agg);
    cudaGetSymbolAddress((void**)&h2,   g_h2);
    cudaGetSymbolAddress((void**)&agg2, g_agg2);
    cudaGetSymbolAddress((void**)&nw,   g_nw);
    cudaGetSymbolAddress((void**)&dgo,  g_degout);
    cudaGetSymbolAddress((void**)&dgi,  g_degin);
    cudaGetSymbolAddress((void**)&dg,   g_deg);

    // smem opt-in for the large GEMM tile (K=128)
    const int smem1 = (64 * (128 + 4) + 128 * 64) * 4;  // 66560 B
    const int smem2 = (64 * (64 + 4)  + 64 * 32)  * 4;  // 25600 B
    const int smem3 = (64 * (32 + 4)  + 32 * 32)  * 4;  // 13312 B
    cudaFuncSetAttribute(gemm_kernel<128, 64, false>,
                         cudaFuncAttributeMaxDynamicSharedMemorySize, smem1);

    const int TB = 256;
    const int gemm_blocks = cdiv(n, 64);

    // ---------- layer 1 : x[128] -> h[64] ----------
    cudaMemsetAsync(dgo, 0, n * sizeof(float), 0);
    cudaMemsetAsync(dgi, 0, n * sizeof(float), 0);
    cudaMemsetAsync(dg,  0, n * sizeof(float), 0);
    cudaMemsetAsync(agg, 0, (size_t)n * 64 * sizeof(float), 0);
    degrees_kernel<<<cdiv(e1, TB), TB>>>(src1, dst1, w1, dgo, dgi, e1);
    norm_kernel<<<cdiv(e1, TB), TB>>>(src1, dst1, w1, nw, dgo, dgi, dg, e1);
    gemm_kernel<128, 64, false><<<gemm_blocks, TB, smem1>>>(x, W1, h, n, nullptr, nullptr);
    scatter_kernel<64><<<cdiv(e1 * 16, TB), TB>>>(src1, dst1, nw, h, agg, e1);
    finalize_kernel<64><<<cdiv(n * 16, TB), TB>>>(agg, dg, b1, h, n);

    // ---------- layer 2 : h[64] -> h2[32] ----------
    cudaMemsetAsync(dgo, 0, n * sizeof(float), 0);
    cudaMemsetAsync(dgi, 0, n * sizeof(float), 0);
    cudaMemsetAsync(dg,  0, n * sizeof(float), 0);
    cudaMemsetAsync(agg2, 0, (size_t)n * 32 * sizeof(float), 0);
    degrees_kernel<<<cdiv(e2, TB), TB>>>(src2, dst2, w2, dgo, dgi, e2);
    norm_kernel<<<cdiv(e2, TB), TB>>>(src2, dst2, w2, nw, dgo, dgi, dg, e2);
    gemm_kernel<64, 32, false><<<gemm_blocks, TB, smem2>>>(h, W2, h2, n, nullptr, nullptr);
    scatter_kernel<32><<<cdiv(e2 * 8, TB), TB>>>(src2, dst2, nw, h2, agg2, e2);
    finalize_kernel<32><<<cdiv(n * 8, TB), TB>>>(agg2, dg, b2, h2, n);

    // ---------- layer 3 : aggregate-first, then (agg @ W3)/deg + b3 ----------
    cudaMemsetAsync(dgo, 0, n * sizeof(float), 0);
    cudaMemsetAsync(dgi, 0, n * sizeof(float), 0);
    cudaMemsetAsync(dg,  0, n * sizeof(float), 0);
    cudaMemsetAsync(agg, 0, (size_t)n * 32 * sizeof(float), 0);
    degrees_kernel<<<cdiv(e3, TB), TB>>>(src3, dst3, w3, dgo, dgi, e3);
    norm_kernel<<<cdiv(e3, TB), TB>>>(src3, dst3, w3, nw, dgo, dgi, dg, e3);
    scatter_kernel<32><<<cdiv(e3 * 8, TB), TB>>>(src3, dst3, nw, h2, agg, e3);
    gemm_kernel<32, 32, true><<<gemm_blocks, TB, smem3>>>(agg, W3, out, n, dg, b3);
}

// round 2
// speedup vs baseline: 1.1967x; 1.1967x over previous
#include <cuda_runtime.h>
#include <cstdint>

#define NNODES 100000
#define NEDGES 1600000
#define EPS 1e-12f

// ---------------- scratch (no allocations allowed) ----------------
__device__ float g_h[NNODES * 64];      // layer1 transformed features
__device__ float g_agg[NNODES * 64];    // layer1 aggregation
__device__ float g_h2[NNODES * 32];     // layer2 output / finalize2 result
__device__ float g_agg2[NNODES * 32];   // layer2 aggregation
__device__ float g_agg3[NNODES * 32];   // layer3 aggregation
__device__ float g_nw1[NEDGES];
__device__ float g_nw2[NEDGES];
__device__ float g_nw3[NEDGES];
__device__ float g_dgo[3 * NNODES];     // out-degree tables (3 layers)
__device__ float g_dgi[3 * NNODES];     // in-degree tables
__device__ float g_deg[3 * NNODES];     // conv 'right' weighted in-degree

// ---------------- fused degree accumulation (all 3 layers) ----------------
__global__ void deg_all_kernel(
    const int* __restrict__ s1, const int* __restrict__ d1, const float* __restrict__ w1,
    const int* __restrict__ s2, const int* __restrict__ d2, const float* __restrict__ w2,
    const int* __restrict__ s3, const int* __restrict__ d3, const float* __restrict__ w3,
    float* __restrict__ dgo, float* __restrict__ dgi, int E)
{
    int e = blockIdx.x * blockDim.x + threadIdx.x;
    if (e >= E) return;
    int a1 = s1[e], b1 = d1[e]; float v1 = w1[e];
    int a2 = s2[e], b2 = d2[e]; float v2 = w2[e];
    int a3 = s3[e], b3 = d3[e]; float v3 = w3[e];
    atomicAdd(&dgo[a1], v1);
    atomicAdd(&dgi[b1], v1);
    atomicAdd(&dgo[NNODES + a2], v2);
    atomicAdd(&dgi[NNODES + b2], v2);
    atomicAdd(&dgo[2 * NNODES + a3], v3);
    atomicAdd(&dgi[2 * NNODES + b3], v3);
}

// ---------------- fused edge-norm + conv-degree (all 3 layers) ----------------
__global__ void norm_all_kernel(
    const int* __restrict__ s1, const int* __restrict__ d1, const float* __restrict__ w1,
    const int* __restrict__ s2, const int* __restrict__ d2, const float* __restrict__ w2,
    const int* __restrict__ s3, const int* __restrict__ d3, const float* __restrict__ w3,
    const float* __restrict__ dgo, const float* __restrict__ dgi,
    float* __restrict__ nw1, float* __restrict__ nw2, float* __restrict__ nw3,
    float* __restrict__ deg, int E)
{
    int e = blockIdx.x * blockDim.x + threadIdx.x;
    if (e >= E) return;
    int a1 = s1[e], b1 = d1[e]; float u1 = w1[e];
    int a2 = s2[e], b2 = d2[e]; float u2 = w2[e];
    int a3 = s3[e], b3 = d3[e]; float u3 = w3[e];
    float o1 = dgo[a1],             i1 = dgi[b1];
    float o2 = dgo[NNODES + a2],    i2 = dgi[NNODES + b2];
    float o3 = dgo[2*NNODES + a3],  i3 = dgi[2*NNODES + b3];
    float v1 = u1 * rsqrtf(fmaxf(o1 * i1, EPS));
    float v2 = u2 * rsqrtf(fmaxf(o2 * i2, EPS));
    float v3 = u3 * rsqrtf(fmaxf(o3 * i3, EPS));
    nw1[e] = v1;
    nw2[e] = v2;
    nw3[e] = v3;
    atomicAdd(&deg[b1], v1);
    atomicAdd(&deg[NNODES + b2], v2);
    atomicAdd(&deg[2*NNODES + b3], v3);
}

// ---------------- edge scatter v2: AGG[dst] += H[src] * nw ----------------
// Each thread owns one 4-float column-chunk of EPT consecutive edges.
// All EPT index loads / gathers issued back-to-back => MLP = EPT.
template <int F, int EPT>
__global__ void scatter_kernel(const int* __restrict__ src, const int* __restrict__ dst,
                               const float* __restrict__ nw, const float* __restrict__ H,
                               float* __restrict__ AGG, int E)
{
    constexpr int TPE = F / 4;
    int t = blockIdx.x * blockDim.x + threadIdx.x;
    int g = t % TPE;
    int e0 = (t / TPE) * EPT;
    if (e0 >= E) return;

    int  s[EPT], d[EPT];
    float w[EPT];
    bool ok[EPT];
#pragma unroll
    for (int k = 0; k < EPT; k++) {
        int e = e0 + k;
        ok[k] = (e < E);
        int ec = ok[k] ? e : (E - 1);
        s[k] = src[ec];
        d[k] = dst[ec];
        w[k] = nw[ec];
    }
    float4 v[EPT];
#pragma unroll
    for (int k = 0; k < EPT; k++)
        v[k] = *(const float4*)&H[(size_t)s[k] * F + g * 4];
#pragma unroll
    for (int k = 0; k < EPT; k++) {
        if (ok[k]) {
            float* p = &AGG[(size_t)d[k] * F + g * 4];
            asm volatile("red.global.add.v4.f32 [%0], {%1, %2, %3, %4};"
                         :: "l"(p), "f"(v[k].x * w[k]), "f"(v[k].y * w[k]),
                            "f"(v[k].z * w[k]), "f"(v[k].w * w[k])
                         : "memory");
        }
    }
}

// ---------------- finalize: OUT = AGG / max(deg,eps) + b ----------------
template <int F>
__global__ void finalize_kernel(const float* __restrict__ AGG, const float* __restrict__ deg,
                                const float* __restrict__ bias, float* __restrict__ OUT, int n)
{
    int t = blockIdx.x * blockDim.x + threadIdx.x;
    int total = n * (F / 4);
    if (t >= total) return;
    int r = t / (F / 4);
    int c = (t % (F / 4)) * 4;
    float inv = 1.0f / fmaxf(deg[r], EPS);
    float4 a = *(const float4*)&AGG[(size_t)r * F + c];
    float4 b4 = *(const float4*)&bias[c];
    float4 o;
    o.x = a.x * inv + b4.x;
    o.y = a.y * inv + b4.y;
    o.z = a.z * inv + b4.z;
    o.w = a.w * inv + b4.w;
    *(float4*)&OUT[(size_t)r * F + c] = o;
}

// ---------------- GEMM: H = f(X) @ W  (M x K @ K x NOUT) ----------------
// FUSEIN: X := X / max(degIn,eps) + biasIn (fused finalize on input)
// FINAL:  output := output / max(degOut,eps) + biasOut (layer-3 epilogue)
template <int K, int NOUT, bool FUSEIN, bool FINAL>
__global__ void __launch_bounds__(256)
gemm_kernel(const float* __restrict__ X, const float* __restrict__ W,
            float* __restrict__ H, int M,
            const float* __restrict__ degIn, const float* __restrict__ biasIn,
            const float* __restrict__ degOut, const float* __restrict__ biasOut)
{
    constexpr int BR = 64;
    constexpr int CT = NOUT / 4;
    constexpr int RT = 256 / CT;
    constexpr int TM = BR / RT;
    constexpr int XS = K + 4;

    extern __shared__ float sm[];
    float* sX = sm;                // BR * XS
    float* sW = sm + BR * XS;      // K * NOUT

    int tid = threadIdx.x;
    int row0 = blockIdx.x * BR;

    constexpr int XV = BR * K / 4;
    for (int i = tid; i < XV; i += 256) {
        int r = (i * 4) / K;
        int c = (i * 4) % K;
        float4 v = make_float4(0.f, 0.f, 0.f, 0.f);
        if (row0 + r < M) {
            v = *(const float4*)&X[(size_t)(row0 + r) * K + c];
            if (FUSEIN) {
                float inv = 1.0f / fmaxf(degIn[row0 + r], EPS);
                float4 b4 = *(const float4*)&biasIn[c];
                v.x = v.x * inv + b4.x;
                v.y = v.y * inv + b4.y;
                v.z = v.z * inv + b4.z;
                v.w = v.w * inv + b4.w;
            }
        }
        *(float4*)&sX[r * XS + c] = v;
    }
    constexpr int WV = K * NOUT / 4;
    for (int i = tid; i < WV; i += 256) {
        *(float4*)&sW[i * 4] = *(const float4*)&W[i * 4];
    }
    __syncthreads();

    int ct = tid % CT;
    int rt = tid / CT;

    float acc[TM][4];
#pragma unroll
    for (int m = 0; m < TM; m++)
#pragma unroll
        for (int j = 0; j < 4; j++) acc[m][j] = 0.f;

#pragma unroll 8
    for (int k = 0; k < K; k++) {
        float4 wv = *(const float4*)&sW[k * NOUT + ct * 4];
#pragma unroll
        for (int m = 0; m < TM; m++) {
            float xv = sX[(rt + m * RT) * XS + k];
            acc[m][0] += xv * wv.x;
            acc[m][1] += xv * wv.y;
            acc[m][2] += xv * wv.z;
            acc[m][3] += xv * wv.w;
        }
    }

#pragma unroll
    for (int m = 0; m < TM; m++) {
        int r = row0 + rt + m * RT;
        if (r < M) {
            float4 o;
            o.x = acc[m][0]; o.y = acc[m][1]; o.z = acc[m][2]; o.w = acc[m][3];
            if (FINAL) {
                float inv = 1.0f / fmaxf(degOut[r], EPS);
                float4 b4 = *(const float4*)&biasOut[ct * 4];
                o.x = o.x * inv + b4.x;
                o.y = o.y * inv + b4.y;
                o.z = o.z * inv + b4.z;
                o.w = o.w * inv + b4.w;
            }
            *(float4*)&H[(size_t)r * NOUT + ct * 4] = o;
        }
    }
}

// ---------------- host ----------------
static inline int cdiv(int a, int b) { return (a + b - 1) / b; }

extern "C" void kernel_launch(void* const* d_in, const int* in_sizes, int n_in,
                              void* d_out, int out_size)
{
    const float* x    = (const float*)d_in[0];
    const int*   src1 = (const int*)d_in[1];
    const int*   dst1 = (const int*)d_in[2];
    const float* w1   = (const float*)d_in[3];
    const int*   src2 = (const int*)d_in[4];
    const int*   dst2 = (const int*)d_in[5];
    const float* w2   = (const float*)d_in[6];
    const int*   src3 = (const int*)d_in[7];
    const int*   dst3 = (const int*)d_in[8];
    const float* w3   = (const float*)d_in[9];
    const float* W1   = (const float*)d_in[10];
    const float* b1   = (const float*)d_in[11];
    const float* W2   = (const float*)d_in[12];
    const float* b2   = (const float*)d_in[13];
    const float* W3   = (const float*)d_in[14];
    const float* b3   = (const float*)d_in[15];
    float* out = (float*)d_out;

    const int n  = in_sizes[0] / 128;
    const int E  = in_sizes[1];

    float *h, *agg, *h2, *agg2, *agg3, *nw1, *nw2, *nw3, *dgo, *dgi, *dg;
    cudaGetSymbolAddress((void**)&h,    g_h);
    cudaGetSymbolAddress((void**)&agg,  g_agg);
    cudaGetSymbolAddress((void**)&h2,   g_h2);
    cudaGetSymbolAddress((void**)&agg2, g_agg2);
    cudaGetSymbolAddress((void**)&agg3, g_agg3);
    cudaGetSymbolAddress((void**)&nw1,  g_nw1);
    cudaGetSymbolAddress((void**)&nw2,  g_nw2);
    cudaGetSymbolAddress((void**)&nw3,  g_nw3);
    cudaGetSymbolAddress((void**)&dgo,  g_dgo);
    cudaGetSymbolAddress((void**)&dgi,  g_dgi);
    cudaGetSymbolAddress((void**)&dg,   g_deg);

    const int smem1 = (64 * (128 + 4) + 128 * 64) * 4;  // 66560 B
    const int smem2 = (64 * (64 + 4)  + 64 * 32)  * 4;  // 25600 B
    const int smem3 = (64 * (32 + 4)  + 32 * 32)  * 4;  // 13312 B
    cudaFuncSetAttribute((const void*)gemm_kernel<128, 64, false, false>,
                         cudaFuncAttributeMaxDynamicSharedMemorySize, smem1);

    const int TB = 256;
    const int gemm_blocks = cdiv(n, 64);
    constexpr int EPT = 4;

    // ---- all memsets up front ----
    cudaMemsetAsync(dgo, 0, 3 * n * sizeof(float), 0);
    cudaMemsetAsync(dgi, 0, 3 * n * sizeof(float), 0);
    cudaMemsetAsync(dg,  0, 3 * n * sizeof(float), 0);
    cudaMemsetAsync(agg,  0, (size_t)n * 64 * sizeof(float), 0);
    cudaMemsetAsync(agg2, 0, (size_t)n * 32 * sizeof(float), 0);
    cudaMemsetAsync(agg3, 0, (size_t)n * 32 * sizeof(float), 0);

    // ---- fused preprocessing for all 3 layers ----
    deg_all_kernel<<<cdiv(E, TB), TB>>>(src1, dst1, w1, src2, dst2, w2,
                                        src3, dst3, w3, dgo, dgi, E);
    norm_all_kernel<<<cdiv(E, TB), TB>>>(src1, dst1, w1, src2, dst2, w2,
                                         src3, dst3, w3, dgo, dgi,
                                         nw1, nw2, nw3, dg, E);

    // ---- layer 1: h = x @ W1 ; agg = scatter ; (finalize fused into gemm2) ----
    gemm_kernel<128, 64, false, false><<<gemm_blocks, TB, smem1>>>(
        x, W1, h, n, nullptr, nullptr, nullptr, nullptr);
    {
        int T = cdiv(E, EPT) * 16;
        scatter_kernel<64, EPT><<<cdiv(T, TB), TB>>>(src1, dst1, nw1, h, agg, E);
    }

    // ---- layer 2: h2 = (agg/deg1 + b1) @ W2 ; agg2 = scatter ; finalize2 ----
    gemm_kernel<64, 32, true, false><<<gemm_blocks, TB, smem2>>>(
        agg, W2, h2, n, dg, b1, nullptr, nullptr);
    {
        int T = cdiv(E, EPT) * 8;
        scatter_kernel<32, EPT><<<cdiv(T, TB), TB>>>(src2, dst2, nw2, h2, agg2, E);
    }
    finalize_kernel<32><<<cdiv(n * 8, TB), TB>>>(agg2, dg + n, b2, h2, n);

    // ---- layer 3: agg3 = scatter(h2) ; out = (agg3 @ W3)/deg3 + b3 ----
    {
        int T = cdiv(E, EPT) * 8;
        scatter_kernel<32, EPT><<<cdiv(T, TB), TB>>>(src3, dst3, nw3, h2, agg3, E);
    }
    gemm_kernel<32, 32, false, true><<<gemm_blocks, TB, smem3>>>(
        agg3, W3, out, n, nullptr, nullptr, dg + 2 * n, b3);
}